// round 4
// baseline (speedup 1.0000x reference)
#include <cuda_runtime.h>

#define T_  128
#define B_  64
#define H_  2048
#define TB_ (T_*B_)      // 8192 rows (M)
#define K0_ 144          // IN*ND
#define L_  4
#define C_  10
#define BM  128
#define BN  128
#define BKK 16
#define BN_EPS 1e-5f

// Scratch (static device globals — allocation-free per harness rules)
__device__ float g_z[(size_t)TB_ * H_];     // 64 MB pre-activation
__device__ float g_h[(size_t)TB_ * H_];     // 64 MB scan output (pre-BN)
__device__ float g_red[2 * H_];             // [sum | sumsq] per channel (zeroed by finalize)
__device__ float g_aff[2 * H_];             // [scale | shift] per channel

// ---------------------------------------------------------------------------
// Tiled fp32 SGEMM (TN): C[m,n] = sum_k A[m,k]*W[n,k] + bias[n]
// A row-major [M,K], W row-major [N,K]. Output to g_z.
// NORM: apply per-k affine (g_aff) to A on load (fused BatchNorm of prev layer).
// Two-stage smem ping-pong with register prefetch to hide global-load latency.
// ---------------------------------------------------------------------------
template<bool NORM>
__global__ __launch_bounds__(256, 2) void gemm_kernel(
    const float* __restrict__ A, const float* __restrict__ W,
    const float* __restrict__ bias, int K)
{
    __shared__ float As[2][BKK][BM + 4];
    __shared__ float Bs[2][BKK][BN + 4];

    const int tid  = threadIdx.x;
    const int m0   = blockIdx.y * BM;
    const int n0   = blockIdx.x * BN;
    const int tx   = tid & 15;        // 16 thread-cols
    const int ty   = tid >> 4;        // 16 thread-rows
    const int lrow = tid >> 2;        // 0..63 loader row
    const int lk4  = (tid & 3) * 4;   // 0,4,8,12 loader k-offset

    const float* Aptr = A + (size_t)(m0 + lrow) * K + lk4;
    const float* Wptr = W + (size_t)(n0 + lrow) * K + lk4;
    const size_t strideA = (size_t)64 * K;   // +64 rows

    float acc[8][8];
    #pragma unroll
    for (int i = 0; i < 8; ++i)
        #pragma unroll
        for (int j = 0; j < 8; ++j) acc[i][j] = 0.f;

    float4 pa0, pa1, pw0, pw1;

    // --- prefetch tile 0 into registers ---
    {
        pa0 = *(const float4*)(Aptr);
        pa1 = *(const float4*)(Aptr + strideA);
        pw0 = *(const float4*)(Wptr);
        pw1 = *(const float4*)(Wptr + strideA);
        if (NORM) {
            const float4 sc = *(const float4*)(g_aff + lk4);
            const float4 sh = *(const float4*)(g_aff + H_ + lk4);
            pa0.x = fmaf(pa0.x, sc.x, sh.x); pa0.y = fmaf(pa0.y, sc.y, sh.y);
            pa0.z = fmaf(pa0.z, sc.z, sh.z); pa0.w = fmaf(pa0.w, sc.w, sh.w);
            pa1.x = fmaf(pa1.x, sc.x, sh.x); pa1.y = fmaf(pa1.y, sc.y, sh.y);
            pa1.z = fmaf(pa1.z, sc.z, sh.z); pa1.w = fmaf(pa1.w, sc.w, sh.w);
        }
    }
    // --- commit tile 0 to smem stage 0 ---
    {
        As[0][lk4 + 0][lrow] = pa0.x; As[0][lk4 + 1][lrow] = pa0.y;
        As[0][lk4 + 2][lrow] = pa0.z; As[0][lk4 + 3][lrow] = pa0.w;
        As[0][lk4 + 0][lrow + 64] = pa1.x; As[0][lk4 + 1][lrow + 64] = pa1.y;
        As[0][lk4 + 2][lrow + 64] = pa1.z; As[0][lk4 + 3][lrow + 64] = pa1.w;
        Bs[0][lk4 + 0][lrow] = pw0.x; Bs[0][lk4 + 1][lrow] = pw0.y;
        Bs[0][lk4 + 2][lrow] = pw0.z; Bs[0][lk4 + 3][lrow] = pw0.w;
        Bs[0][lk4 + 0][lrow + 64] = pw1.x; Bs[0][lk4 + 1][lrow + 64] = pw1.y;
        Bs[0][lk4 + 2][lrow + 64] = pw1.z; Bs[0][lk4 + 3][lrow + 64] = pw1.w;
    }
    __syncthreads();

    int cur = 0;
    for (int kt = BKK; kt <= K; kt += BKK) {
        const bool has_next = (kt < K);

        // --- prefetch next tile into registers (overlaps with compute below) ---
        if (has_next) {
            pa0 = *(const float4*)(Aptr + kt);
            pa1 = *(const float4*)(Aptr + strideA + kt);
            pw0 = *(const float4*)(Wptr + kt);
            pw1 = *(const float4*)(Wptr + strideA + kt);
            if (NORM) {
                const float4 sc = *(const float4*)(g_aff + kt + lk4);
                const float4 sh = *(const float4*)(g_aff + H_ + kt + lk4);
                pa0.x = fmaf(pa0.x, sc.x, sh.x); pa0.y = fmaf(pa0.y, sc.y, sh.y);
                pa0.z = fmaf(pa0.z, sc.z, sh.z); pa0.w = fmaf(pa0.w, sc.w, sh.w);
                pa1.x = fmaf(pa1.x, sc.x, sh.x); pa1.y = fmaf(pa1.y, sc.y, sh.y);
                pa1.z = fmaf(pa1.z, sc.z, sh.z); pa1.w = fmaf(pa1.w, sc.w, sh.w);
            }
        }

        // --- compute on current stage ---
        #pragma unroll
        for (int kk = 0; kk < BKK; ++kk) {
            float a[8], b[8];
            *(float4*)(a)     = *(const float4*)(&As[cur][kk][ty * 8]);
            *(float4*)(a + 4) = *(const float4*)(&As[cur][kk][ty * 8 + 4]);
            *(float4*)(b)     = *(const float4*)(&Bs[cur][kk][tx * 8]);
            *(float4*)(b + 4) = *(const float4*)(&Bs[cur][kk][tx * 8 + 4]);
            #pragma unroll
            for (int i = 0; i < 8; ++i)
                #pragma unroll
                for (int j = 0; j < 8; ++j)
                    acc[i][j] = fmaf(a[i], b[j], acc[i][j]);
        }

        // --- commit prefetched tile to the other stage ---
        if (has_next) {
            const int nxt = cur ^ 1;
            As[nxt][lk4 + 0][lrow] = pa0.x; As[nxt][lk4 + 1][lrow] = pa0.y;
            As[nxt][lk4 + 2][lrow] = pa0.z; As[nxt][lk4 + 3][lrow] = pa0.w;
            As[nxt][lk4 + 0][lrow + 64] = pa1.x; As[nxt][lk4 + 1][lrow + 64] = pa1.y;
            As[nxt][lk4 + 2][lrow + 64] = pa1.z; As[nxt][lk4 + 3][lrow + 64] = pa1.w;
            Bs[nxt][lk4 + 0][lrow] = pw0.x; Bs[nxt][lk4 + 1][lrow] = pw0.y;
            Bs[nxt][lk4 + 2][lrow] = pw0.z; Bs[nxt][lk4 + 3][lrow] = pw0.w;
            Bs[nxt][lk4 + 0][lrow + 64] = pw1.x; Bs[nxt][lk4 + 1][lrow + 64] = pw1.y;
            Bs[nxt][lk4 + 2][lrow + 64] = pw1.z; Bs[nxt][lk4 + 3][lrow + 64] = pw1.w;
            __syncthreads();
            cur = nxt;
        }
    }

    const float4 bl = *(const float4*)(bias + n0 + tx * 8);
    const float4 bh = *(const float4*)(bias + n0 + tx * 8 + 4);
    #pragma unroll
    for (int i = 0; i < 8; ++i) {
        const int m = m0 + ty * 8 + i;
        float4 o0 = make_float4(acc[i][0] + bl.x, acc[i][1] + bl.y,
                                acc[i][2] + bl.z, acc[i][3] + bl.w);
        float4 o1 = make_float4(acc[i][4] + bh.x, acc[i][5] + bh.y,
                                acc[i][6] + bh.z, acc[i][7] + bh.w);
        *(float4*)(g_z + (size_t)m * H_ + n0 + tx * 8)     = o0;
        *(float4*)(g_z + (size_t)m * H_ + n0 + tx * 8 + 4) = o1;
    }
}

// ---------------------------------------------------------------------------
// IndRNN scan over T, fused with BN-statistics accumulation.
// One thread per (b,h). z layout: [T, B*H] contiguous, coalesced per timestep.
// ---------------------------------------------------------------------------
__global__ __launch_bounds__(256) void scan_kernel(const float* __restrict__ us_l)
{
    const int idx = blockIdx.x * blockDim.x + threadIdx.x;  // 0..131071
    const int ch  = idx & (H_ - 1);
    const float u = us_l[ch];
    float h = 0.f, s = 0.f, s2 = 0.f;
    #pragma unroll 4
    for (int t = 0; t < T_; ++t) {
        const float v = g_z[(size_t)t * (B_ * H_) + idx];
        h = fmaxf(fmaf(u, h, v), 0.f);
        g_h[(size_t)t * (B_ * H_) + idx] = h;
        s += h;
        s2 = fmaf(h, h, s2);
    }
    atomicAdd(&g_red[ch], s);
    atomicAdd(&g_red[H_ + ch], s2);
}

// ---------------------------------------------------------------------------
// Turn (sum, sumsq) into (scale, shift) for BN; re-zero stats for next use
// (keeps every kernel_launch call self-consistent across graph replays).
// ---------------------------------------------------------------------------
__global__ void finalize_kernel(const float* __restrict__ gammas_l,
                                const float* __restrict__ betas_l)
{
    const int ch = blockIdx.x * blockDim.x + threadIdx.x;
    const float s  = g_red[ch];
    const float s2 = g_red[H_ + ch];
    const float mean = s * (1.f / TB_);
    const float var  = s2 * (1.f / TB_) - mean * mean;
    const float scale = gammas_l[ch] * rsqrtf(var + BN_EPS);
    g_aff[ch]       = scale;
    g_aff[H_ + ch]  = fmaf(-mean, scale, betas_l[ch]);
    g_red[ch]       = 0.f;
    g_red[H_ + ch]  = 0.f;
}

// ---------------------------------------------------------------------------
// out[b,c] = sum_h BN(h[T-1,b,h]) * Wlast[c,h] + blast[c]
// ---------------------------------------------------------------------------
__global__ __launch_bounds__(256) void final_kernel(
    const float* __restrict__ Wlast, const float* __restrict__ blast,
    float* __restrict__ out)
{
    const int b = blockIdx.x;
    const int tid = threadIdx.x;
    float acc[C_];
    #pragma unroll
    for (int c = 0; c < C_; ++c) acc[c] = 0.f;

    const float* hrow = g_h + (size_t)(T_ - 1) * B_ * H_ + (size_t)b * H_;
    for (int h = tid; h < H_; h += 256) {
        const float v = fmaf(hrow[h], g_aff[h], g_aff[H_ + h]);
        #pragma unroll
        for (int c = 0; c < C_; ++c)
            acc[c] = fmaf(v, Wlast[c * H_ + h], acc[c]);
    }

    __shared__ float red[C_][256];
    #pragma unroll
    for (int c = 0; c < C_; ++c) red[c][tid] = acc[c];
    __syncthreads();
    for (int s = 128; s > 0; s >>= 1) {
        if (tid < s) {
            #pragma unroll
            for (int c = 0; c < C_; ++c) red[c][tid] += red[c][tid + s];
        }
        __syncthreads();
    }
    if (tid < C_) out[b * C_ + tid] = red[tid][0] + blast[tid];
}

// ---------------------------------------------------------------------------
extern "C" void kernel_launch(void* const* d_in, const int* in_sizes, int n_in,
                              void* d_out, int out_size)
{
    const float* x      = (const float*)d_in[0];  // [T,B,IN,ND] = [8192,144]
    const float* W0     = (const float*)d_in[1];  // [H,144]
    const float* Ws     = (const float*)d_in[2];  // [L-1,H,H]
    const float* bs     = (const float*)d_in[3];  // [L,H]
    const float* us     = (const float*)d_in[4];  // [L,H]
    const float* gammas = (const float*)d_in[5];  // [L,H]
    const float* betas  = (const float*)d_in[6];  // [L,H]
    const float* Wlast  = (const float*)d_in[7];  // [C,H]
    const float* blast  = (const float*)d_in[8];  // [C]
    float* out = (float*)d_out;                   // [B,C]

    float* gh = nullptr;
    cudaGetSymbolAddress((void**)&gh, g_h);

    const dim3 ggrid(H_ / BN, TB_ / BM);  // 16 x 64 blocks

    // Layer 0 (K=144, raw input)
    gemm_kernel<false><<<ggrid, 256>>>(x, W0, bs, K0_);
    scan_kernel<<<(B_ * H_) / 256, 256>>>(us);
    finalize_kernel<<<H_ / 256, 256>>>(gammas, betas);

    // Layers 1..3 (K=2048, BN of previous layer fused into A-load)
    for (int l = 1; l < L_; ++l) {
        gemm_kernel<true><<<ggrid, 256>>>(gh, Ws + (size_t)(l - 1) * H_ * H_,
                                          bs + (size_t)l * H_, H_);
        scan_kernel<<<(B_ * H_) / 256, 256>>>(us + (size_t)l * H_);
        finalize_kernel<<<H_ / 256, 256>>>(gammas + (size_t)l * H_,
                                           betas + (size_t)l * H_);
    }

    // Classifier on BN(h[T-1])
    final_kernel<<<B_, 256>>>(Wlast, blast, out);
}

// round 12
// speedup vs baseline: 1.7232x; 1.7232x over previous
#include <cuda_runtime.h>
#include <cuda_bf16.h>
#include <mma.h>
#include <cstdint>

using namespace nvcuda;

#define T_  128
#define B_  64
#define H_  2048
#define TB_ (T_*B_)      // 8192 rows (M)
#define K0_ 144
#define L_  4
#define C_  10
#define BN_EPS 1e-5f
#define KC2 32           // K chunk (bf16 elems) per smem stage
#define NCH (H_/KC2)     // 64 chunks
#define LDA 40           // padded smem stride (elems); 80 B = 16B multiple (WMMA-legal)

// Scratch (static device globals — allocation-free per harness rules)
__device__ float g_z[(size_t)TB_ * H_];
__device__ float g_h[(size_t)TB_ * H_];
__device__ float g_red[2 * H_];
__device__ float g_aff[2 * H_];
__device__ float g_zero[H_];                                 // stays zero
__device__ __nv_bfloat16 g_Whi[(size_t)(L_ - 1) * H_ * H_];  // 24 MB
__device__ __nv_bfloat16 g_Wlo[(size_t)(L_ - 1) * H_ * H_];  // 24 MB

__device__ __forceinline__ void split4(float4 v, uint32_t& hi01, uint32_t& hi23,
                                       uint32_t& lo01, uint32_t& lo23) {
    __nv_bfloat16 h0 = __float2bfloat16(v.x), h1 = __float2bfloat16(v.y),
                  h2 = __float2bfloat16(v.z), h3 = __float2bfloat16(v.w);
    __nv_bfloat16 l0 = __float2bfloat16(v.x - __bfloat162float(h0));
    __nv_bfloat16 l1 = __float2bfloat16(v.y - __bfloat162float(h1));
    __nv_bfloat16 l2 = __float2bfloat16(v.z - __bfloat162float(h2));
    __nv_bfloat16 l3 = __float2bfloat16(v.w - __bfloat162float(h3));
    hi01 = (uint32_t)__bfloat16_as_ushort(h0) | ((uint32_t)__bfloat16_as_ushort(h1) << 16);
    hi23 = (uint32_t)__bfloat16_as_ushort(h2) | ((uint32_t)__bfloat16_as_ushort(h3) << 16);
    lo01 = (uint32_t)__bfloat16_as_ushort(l0) | ((uint32_t)__bfloat16_as_ushort(l1) << 16);
    lo23 = (uint32_t)__bfloat16_as_ushort(l2) | ((uint32_t)__bfloat16_as_ushort(l3) << 16);
}

// ---------------------------------------------------------------------------
// One-shot W split: Ws [3,H,H] fp32 -> g_Whi/g_Wlo bf16, same row-major layout
// ---------------------------------------------------------------------------
__global__ __launch_bounds__(256) void convW_kernel(const float* __restrict__ Ws)
{
    const size_t idx = (size_t)blockIdx.x * 256 + threadIdx.x;  // float4 index
    const float4 w = ((const float4*)Ws)[idx];
    uint32_t h01, h23, l01, l23;
    split4(w, h01, h23, l01, l23);
    ((uint2*)g_Whi)[idx] = make_uint2(h01, h23);
    ((uint2*)g_Wlo)[idx] = make_uint2(l01, l23);
}

// ---------------------------------------------------------------------------
// bf16 WMMA GEMM (layers 1..3): z[m,n] = sum_k BN(A[m,k]) * W[n,k]
// 3-term precision split: a_hi*w_hi + a_hi*w_lo + a_lo*w_hi, fp32 accum.
// Bias is added later in scan_kernel (channel-indexed).
// CTA: 128x128 tile, 8 warps (4x2), warp tile 32x64, K chunked by 32.
// ---------------------------------------------------------------------------
__global__ __launch_bounds__(256) void gemm_wmma(
    const float* __restrict__ A,
    const __nv_bfloat16* __restrict__ Whi, const __nv_bfloat16* __restrict__ Wlo)
{
    __shared__ __nv_bfloat16 sAhi[128][LDA];
    __shared__ __nv_bfloat16 sAlo[128][LDA];
    __shared__ __nv_bfloat16 sWhi[128][LDA];
    __shared__ __nv_bfloat16 sWlo[128][LDA];

    const int tid = threadIdx.x, wid = tid >> 5;
    const int m0 = blockIdx.y * 128, n0 = blockIdx.x * 128;
    const int wm = (wid & 3) * 32;   // warp M offset: 0,32,64,96
    const int wn = (wid >> 2) * 64;  // warp N offset: 0,64

    wmma::fragment<wmma::accumulator, 16, 16, 16, float> acc[2][4];
    #pragma unroll
    for (int i = 0; i < 2; ++i)
        #pragma unroll
        for (int j = 0; j < 4; ++j) wmma::fill_fragment(acc[i][j], 0.0f);

    for (int c = 0; c < NCH; ++c) {
        const int k0 = c * KC2;
        __syncthreads();   // prior-iteration fragment reads done before overwrite

        // Stage chunk: 128 rows x 32 k of each matrix (1024 float4-groups / matrix)
        #pragma unroll
        for (int it = 0; it < 4; ++it) {
            const int idx = tid + it * 256;   // 0..1023
            const int row = idx >> 3;         // 0..127
            const int g   = idx & 7;          // 0..7 (4-elem groups along k)
            const int kk  = k0 + g * 4;

            float4 va = *(const float4*)(A + (size_t)(m0 + row) * H_ + kk);
            const float4 sc = *(const float4*)(g_aff + kk);
            const float4 sh = *(const float4*)(g_aff + H_ + kk);
            va.x = fmaf(va.x, sc.x, sh.x); va.y = fmaf(va.y, sc.y, sh.y);
            va.z = fmaf(va.z, sc.z, sh.z); va.w = fmaf(va.w, sc.w, sh.w);
            uint32_t h01, h23, l01, l23;
            split4(va, h01, h23, l01, l23);
            *(uint2*)&sAhi[row][g * 4] = make_uint2(h01, h23);
            *(uint2*)&sAlo[row][g * 4] = make_uint2(l01, l23);

            *(uint2*)&sWhi[row][g * 4] =
                *(const uint2*)(Whi + (size_t)(n0 + row) * H_ + kk);
            *(uint2*)&sWlo[row][g * 4] =
                *(const uint2*)(Wlo + (size_t)(n0 + row) * H_ + kk);
        }
        __syncthreads();

        #pragma unroll
        for (int kk = 0; kk < 2; ++kk) {   // two k16 steps per chunk
            wmma::fragment<wmma::matrix_b, 16, 16, 16, __nv_bfloat16, wmma::col_major> bh[4], bl[4];
            #pragma unroll
            for (int n = 0; n < 4; ++n) {
                wmma::load_matrix_sync(bh[n], &sWhi[wn + n * 16][kk * 16], LDA);
                wmma::load_matrix_sync(bl[n], &sWlo[wn + n * 16][kk * 16], LDA);
            }
            #pragma unroll
            for (int m = 0; m < 2; ++m) {
                wmma::fragment<wmma::matrix_a, 16, 16, 16, __nv_bfloat16, wmma::row_major> ah, al;
                wmma::load_matrix_sync(ah, &sAhi[wm + m * 16][kk * 16], LDA);
                wmma::load_matrix_sync(al, &sAlo[wm + m * 16][kk * 16], LDA);
                #pragma unroll
                for (int n = 0; n < 4; ++n) {
                    wmma::mma_sync(acc[m][n], ah, bh[n], acc[m][n]);
                    wmma::mma_sync(acc[m][n], ah, bl[n], acc[m][n]);
                    wmma::mma_sync(acc[m][n], al, bh[n], acc[m][n]);
                }
            }
        }
    }

    // Epilogue: store fp32 tiles directly to g_z (bias added in scan)
    #pragma unroll
    for (int m = 0; m < 2; ++m)
        #pragma unroll
        for (int n = 0; n < 4; ++n)
            wmma::store_matrix_sync(
                g_z + (size_t)(m0 + wm + m * 16) * H_ + (n0 + wn + n * 16),
                acc[m][n], H_, wmma::mem_row_major);
}

// ---------------------------------------------------------------------------
// fp32 SGEMM for layer 0 only (K=144, no norm): verified R4 kernel (adds bias)
// ---------------------------------------------------------------------------
__global__ __launch_bounds__(256, 2) void gemm0_kernel(
    const float* __restrict__ A, const float* __restrict__ W,
    const float* __restrict__ bias, int K)
{
    __shared__ float As[2][16][128 + 4];
    __shared__ float Bs[2][16][128 + 4];

    const int tid  = threadIdx.x;
    const int m0   = blockIdx.y * 128;
    const int n0   = blockIdx.x * 128;
    const int tx   = tid & 15;
    const int ty   = tid >> 4;
    const int lrow = tid >> 2;
    const int lk4  = (tid & 3) * 4;

    const float* Aptr = A + (size_t)(m0 + lrow) * K + lk4;
    const float* Wptr = W + (size_t)(n0 + lrow) * K + lk4;
    const size_t strideA = (size_t)64 * K;

    float acc[8][8];
    #pragma unroll
    for (int i = 0; i < 8; ++i)
        #pragma unroll
        for (int j = 0; j < 8; ++j) acc[i][j] = 0.f;

    float4 pa0 = *(const float4*)(Aptr);
    float4 pa1 = *(const float4*)(Aptr + strideA);
    float4 pw0 = *(const float4*)(Wptr);
    float4 pw1 = *(const float4*)(Wptr + strideA);
    As[0][lk4+0][lrow] = pa0.x; As[0][lk4+1][lrow] = pa0.y;
    As[0][lk4+2][lrow] = pa0.z; As[0][lk4+3][lrow] = pa0.w;
    As[0][lk4+0][lrow+64] = pa1.x; As[0][lk4+1][lrow+64] = pa1.y;
    As[0][lk4+2][lrow+64] = pa1.z; As[0][lk4+3][lrow+64] = pa1.w;
    Bs[0][lk4+0][lrow] = pw0.x; Bs[0][lk4+1][lrow] = pw0.y;
    Bs[0][lk4+2][lrow] = pw0.z; Bs[0][lk4+3][lrow] = pw0.w;
    Bs[0][lk4+0][lrow+64] = pw1.x; Bs[0][lk4+1][lrow+64] = pw1.y;
    Bs[0][lk4+2][lrow+64] = pw1.z; Bs[0][lk4+3][lrow+64] = pw1.w;
    __syncthreads();

    int cur = 0;
    for (int kt = 16; kt <= K; kt += 16) {
        const bool has_next = (kt < K);
        if (has_next) {
            pa0 = *(const float4*)(Aptr + kt);
            pa1 = *(const float4*)(Aptr + strideA + kt);
            pw0 = *(const float4*)(Wptr + kt);
            pw1 = *(const float4*)(Wptr + strideA + kt);
        }
        #pragma unroll
        for (int kk = 0; kk < 16; ++kk) {
            float a[8], b[8];
            *(float4*)(a)     = *(const float4*)(&As[cur][kk][ty * 8]);
            *(float4*)(a + 4) = *(const float4*)(&As[cur][kk][ty * 8 + 4]);
            *(float4*)(b)     = *(const float4*)(&Bs[cur][kk][tx * 8]);
            *(float4*)(b + 4) = *(const float4*)(&Bs[cur][kk][tx * 8 + 4]);
            #pragma unroll
            for (int i = 0; i < 8; ++i)
                #pragma unroll
                for (int j = 0; j < 8; ++j)
                    acc[i][j] = fmaf(a[i], b[j], acc[i][j]);
        }
        if (has_next) {
            const int nxt = cur ^ 1;
            As[nxt][lk4+0][lrow] = pa0.x; As[nxt][lk4+1][lrow] = pa0.y;
            As[nxt][lk4+2][lrow] = pa0.z; As[nxt][lk4+3][lrow] = pa0.w;
            As[nxt][lk4+0][lrow+64] = pa1.x; As[nxt][lk4+1][lrow+64] = pa1.y;
            As[nxt][lk4+2][lrow+64] = pa1.z; As[nxt][lk4+3][lrow+64] = pa1.w;
            Bs[nxt][lk4+0][lrow] = pw0.x; Bs[nxt][lk4+1][lrow] = pw0.y;
            Bs[nxt][lk4+2][lrow] = pw0.z; Bs[nxt][lk4+3][lrow] = pw0.w;
            Bs[nxt][lk4+0][lrow+64] = pw1.x; Bs[nxt][lk4+1][lrow+64] = pw1.y;
            Bs[nxt][lk4+2][lrow+64] = pw1.z; Bs[nxt][lk4+3][lrow+64] = pw1.w;
            __syncthreads();
            cur = nxt;
        }
    }

    const float4 bl = *(const float4*)(bias + n0 + tx * 8);
    const float4 bh = *(const float4*)(bias + n0 + tx * 8 + 4);
    #pragma unroll
    for (int i = 0; i < 8; ++i) {
        const int m = m0 + ty * 8 + i;
        float4 o0 = make_float4(acc[i][0] + bl.x, acc[i][1] + bl.y,
                                acc[i][2] + bl.z, acc[i][3] + bl.w);
        float4 o1 = make_float4(acc[i][4] + bh.x, acc[i][5] + bh.y,
                                acc[i][6] + bh.z, acc[i][7] + bh.w);
        *(float4*)(g_z + (size_t)m * H_ + n0 + tx * 8)     = o0;
        *(float4*)(g_z + (size_t)m * H_ + n0 + tx * 8 + 4) = o1;
    }
}

// ---------------------------------------------------------------------------
// IndRNN scan over T with per-channel bias add, fused BN-stat accumulation.
// ---------------------------------------------------------------------------
__global__ __launch_bounds__(256) void scan_kernel(const float* __restrict__ us_l,
                                                   const float* __restrict__ bias_l)
{
    const int idx = blockIdx.x * blockDim.x + threadIdx.x;
    const int ch  = idx & (H_ - 1);
    const float u = us_l[ch];
    const float b = bias_l[ch];
    float h = 0.f, s = 0.f, s2 = 0.f;
    #pragma unroll 4
    for (int t = 0; t < T_; ++t) {
        const float v = g_z[(size_t)t * (B_ * H_) + idx] + b;
        h = fmaxf(fmaf(u, h, v), 0.f);
        g_h[(size_t)t * (B_ * H_) + idx] = h;
        s += h;
        s2 = fmaf(h, h, s2);
    }
    atomicAdd(&g_red[ch], s);
    atomicAdd(&g_red[H_ + ch], s2);
}

__global__ void finalize_kernel(const float* __restrict__ gammas_l,
                                const float* __restrict__ betas_l)
{
    const int ch = blockIdx.x * blockDim.x + threadIdx.x;
    const float s  = g_red[ch];
    const float s2 = g_red[H_ + ch];
    const float mean = s * (1.f / TB_);
    const float var  = s2 * (1.f / TB_) - mean * mean;
    const float scale = gammas_l[ch] * rsqrtf(var + BN_EPS);
    g_aff[ch]      = scale;
    g_aff[H_ + ch] = fmaf(-mean, scale, betas_l[ch]);
    g_red[ch]      = 0.f;
    g_red[H_ + ch] = 0.f;
}

__global__ __launch_bounds__(256) void final_kernel(
    const float* __restrict__ Wlast, const float* __restrict__ blast,
    float* __restrict__ out)
{
    const int b = blockIdx.x;
    const int tid = threadIdx.x;
    float acc[C_];
    #pragma unroll
    for (int c = 0; c < C_; ++c) acc[c] = 0.f;

    const float* hrow = g_h + (size_t)(T_ - 1) * B_ * H_ + (size_t)b * H_;
    for (int h = tid; h < H_; h += 256) {
        const float v = fmaf(hrow[h], g_aff[h], g_aff[H_ + h]);
        #pragma unroll
        for (int c = 0; c < C_; ++c)
            acc[c] = fmaf(v, Wlast[c * H_ + h], acc[c]);
    }
    __shared__ float red[C_][256];
    #pragma unroll
    for (int c = 0; c < C_; ++c) red[c][tid] = acc[c];
    __syncthreads();
    for (int s = 128; s > 0; s >>= 1) {
        if (tid < s) {
            #pragma unroll
            for (int c = 0; c < C_; ++c) red[c][tid] += red[c][tid + s];
        }
        __syncthreads();
    }
    if (tid < C_) out[b * C_ + tid] = red[tid][0] + blast[tid];
}

// ---------------------------------------------------------------------------
extern "C" void kernel_launch(void* const* d_in, const int* in_sizes, int n_in,
                              void* d_out, int out_size)
{
    const float* x      = (const float*)d_in[0];
    const float* W0     = (const float*)d_in[1];
    const float* Ws     = (const float*)d_in[2];
    const float* bs     = (const float*)d_in[3];
    const float* us     = (const float*)d_in[4];
    const float* gammas = (const float*)d_in[5];
    const float* betas  = (const float*)d_in[6];
    const float* Wlast  = (const float*)d_in[7];
    const float* blast  = (const float*)d_in[8];
    float* out = (float*)d_out;

    float* gh = nullptr;
    cudaGetSymbolAddress((void**)&gh, g_h);
    float* gz0 = nullptr;
    cudaGetSymbolAddress((void**)&gz0, g_zero);
    __nv_bfloat16* whi = nullptr;
    cudaGetSymbolAddress((void**)&whi, g_Whi);
    __nv_bfloat16* wlo = nullptr;
    cudaGetSymbolAddress((void**)&wlo, g_Wlo);

    const dim3 g0(H_ / 128, TB_ / 128);   // 16 x 64

    // Pre-split recurrent weights to bf16 hi/lo
    convW_kernel<<<(int)(((size_t)(L_ - 1) * H_ * H_ / 4) / 256), 256>>>(Ws);

    // Layer 0: fp32 (K=144), bias added in GEMM -> scan gets zero bias
    gemm0_kernel<<<g0, 256>>>(x, W0, bs, K0_);
    scan_kernel<<<(B_ * H_) / 256, 256>>>(us, gz0);
    finalize_kernel<<<H_ / 256, 256>>>(gammas, betas);

    // Layers 1..3: bf16-split WMMA GEMM (BN fused on A-load; bias in scan)
    for (int l = 1; l < L_; ++l) {
        gemm_wmma<<<g0, 256>>>(gh,
                               whi + (size_t)(l - 1) * H_ * H_,
                               wlo + (size_t)(l - 1) * H_ * H_);
        scan_kernel<<<(B_ * H_) / 256, 256>>>(us + (size_t)l * H_,
                                              bs + (size_t)l * H_);
        finalize_kernel<<<H_ / 256, 256>>>(gammas + (size_t)l * H_,
                                           betas + (size_t)l * H_);
    }

    final_kernel<<<B_, 256>>>(Wlast, blast, out);
}